// round 12
// baseline (speedup 1.0000x reference)
#include <cuda_runtime.h>
#include <cuda_bf16.h>
#include <stdint.h>

#define B_TOT 16384
#define V_STEPS 20

// ---- activation buffers: packed bf16 pair (hi<<16 | lo) per element ----
__device__ uint32_t g_xin[B_TOT*288];
__device__ uint32_t g_x1[B_TOT*1024];
__device__ uint32_t g_x2[B_TOT*1024];
__device__ uint32_t g_x3[B_TOT*512];
__device__ uint32_t g_x4[B_TOT*256];
// MLP weights bf16 planes [hl][N][Kp] per layer, concatenated
#define WO1 0
#define WO2 589824
#define WO3 (WO2+2097152)
#define WO4 (WO3+1048576)
__device__ __align__(16) unsigned short g_Wm[WO4+262144];
// GRU packed weights bf16 [hl][768][272] (+pad for tail staging)
__device__ __align__(16) unsigned short g_Wg[2*768*272 + 64];
__device__ __align__(16) unsigned short g_Wxn[2*256*16];
__device__ uint32_t g_hstage[128*128*256];

// GRU smem offsets
#define OFF_A_HI 0
#define OFF_A_LO 71680
#define OFF_BXN  143360
#define OFF_BS   167936            // [2buf][12 blk][32 rows][80B] = 61440
#define GRU_SMEM 229376
#define MLP_SMEM 81920

__device__ __forceinline__ float sigmoidf_(float x){ return __fdividef(1.f,1.f+__expf(-x)); }
__device__ __forceinline__ float tanh_(float x){ return __fdividef(2.f,1.f+__expf(-2.f*x))-1.f; }
__device__ __forceinline__ uint32_t smem_u32(const void* p){
    uint32_t a; asm("{ .reg .u64 t; cvta.to.shared.u64 t, %1; cvt.u32.u64 %0, t; }":"=r"(a):"l"(p)); return a;
}
__device__ __forceinline__ void ldsm4(uint32_t a, uint32_t* r){
    asm volatile("ldmatrix.sync.aligned.m8n8.x4.shared.b16 {%0,%1,%2,%3}, [%4];"
        : "=r"(r[0]),"=r"(r[1]),"=r"(r[2]),"=r"(r[3]) : "r"(a));
}
__device__ __forceinline__ void ldsm2(uint32_t a, uint32_t* r){
    asm volatile("ldmatrix.sync.aligned.m8n8.x2.shared.b16 {%0,%1}, [%2];"
        : "=r"(r[0]),"=r"(r[1]) : "r"(a));
}
__device__ __forceinline__ void mma16816(float* d, const uint32_t* a, const uint32_t* b){
    asm volatile("mma.sync.aligned.m16n8k16.row.col.f32.bf16.bf16.f32 "
        "{%0,%1,%2,%3}, {%4,%5,%6,%7}, {%8,%9}, {%0,%1,%2,%3};"
        : "+f"(d[0]),"+f"(d[1]),"+f"(d[2]),"+f"(d[3])
        : "r"(a[0]),"r"(a[1]),"r"(a[2]),"r"(a[3]),"r"(b[0]),"r"(b[1]));
}
__device__ __forceinline__ void cp16(uint32_t dst, const void* src){
    asm volatile("cp.async.cg.shared.global [%0], [%1], 16;"::"r"(dst),"l"(src));
}
#define CP_COMMIT() asm volatile("cp.async.commit_group;":::"memory")
#define CP_WAIT0()  asm volatile("cp.async.wait_group 0;":::"memory")
__device__ __forceinline__ void bfsplit(float v, unsigned short& h, unsigned short& l){
    __nv_bfloat16 hh=__float2bfloat16(v);
    h=__bfloat16_as_ushort(hh);
    l=__bfloat16_as_ushort(__float2bfloat16(v-__bfloat162float(hh)));
}
__device__ __forceinline__ uint32_t bfpack(float v){
    unsigned short h,l; bfsplit(v,h,l); return ((uint32_t)h<<16)|l;
}
__device__ __forceinline__ float bfunpk(uint32_t p){
    unsigned short h=(unsigned short)(p>>16), l=(unsigned short)(p&0xffffu);
    return __bfloat162float(*(__nv_bfloat16*)&h)+__bfloat162float(*(__nv_bfloat16*)&l);
}

// ---------------- pack kernels ----------------
__global__ void pack_gru(const float* __restrict__ W_ih, const float* __restrict__ W_hh,
                         const float* __restrict__ b_ih, const float* __restrict__ b_hh){
    int g=blockIdx.x, k=threadIdx.x;
    int gate=g>>8;
    float v;
    if(k<15)       v = (gate==2)? 0.f : W_ih[g*15+k];
    else if(k==15) v = (gate==2)? b_hh[g] : (b_ih[g]+b_hh[g]);
    else           v = W_hh[g*256+(k-16)];
    unsigned short h,l; bfsplit(v,h,l);
    g_Wg[g*272+k]=h; g_Wg[208896+g*272+k]=l;
    if(g>=512 && k<16){
        float w = (k<15)? W_ih[g*15+k] : b_ih[g];
        unsigned short h2,l2; bfsplit(w,h2,l2);
        g_Wxn[(g-512)*16+k]=h2; g_Wxn[4096+(g-512)*16+k]=l2;
    }
}
__global__ void pack_mlp(const float* __restrict__ W, unsigned short* __restrict__ dst,
                         int N, int K, int Kp, int l1mode){
    int n=blockIdx.x;
    for(int k=threadIdx.x;k<Kp;k+=256){
        float v=0.f;
        if(l1mode){ if(k<15) v=W[n*271+k]; else if(k>=16&&k<272) v=W[n*271+k-1]; }
        else if(k<K) v=W[(size_t)n*K+k];
        unsigned short h,l; bfsplit(v,h,l);
        dst[(size_t)n*Kp+k]=h;
        dst[(size_t)N*Kp+(size_t)n*Kp+k]=l;
    }
}

// ---------------- GRU: mma.sync bf16-split, paired-N passes + cp.async ----------------
__global__ __launch_bounds__(256,1) void gru_mma_kernel(const float* __restrict__ state){
    extern __shared__ __align__(16) unsigned char sm[];
    const uint32_t sb=smem_u32(sm);
    const int tid=threadIdx.x, wid=tid>>5, l=tid&31, ll=l&15;
    const int wm=wid&1, wn=wid>>1;
    const int cta=blockIdx.x, bbase=cta*128;

    for(int i=tid;i<143360/16;i+=256) ((uint4*)sm)[i]=make_uint4(0,0,0,0);
    for(int i=tid;i<1024;i+=256){
        int u=i&1, n=(i>>1)&255, hl=i>>9;
        uint4 v=*(const uint4*)(g_Wxn + hl*4096 + n*16 + u*8);
        *(uint4*)(sm+OFF_BXN + hl*12288 + n*48 + u*16)=v;
    }
    __syncthreads();

    const uint32_t aoff  = (uint32_t)(ll*560 + (l>>4)*16);
    const uint32_t boffn = (uint32_t)((l&7)*80 + (ll>>3)*16) + wn*8*80;
    const uint32_t bxoff = (uint32_t)((l&7)*48 + (ll>>3)*16) + wn*8*48;

    // staging decode (constant per thread): 6 units of 16B per thread per chunk
    int su[6],sn[6],sblk[6],sg[6],shl[6],sp[6];
    #pragma unroll
    for(int j=0;j<6;j++){
        int i=tid+j*256;
        su[j]=i&3; sn[j]=(i>>2)&31; sblk[j]=i>>7;
        sp[j]=sblk[j]/6; int rem=sblk[j]-sp[j]*6; sg[j]=rem>>1; shl[j]=rem&1;
    }

    for(int t=0;t<V_STEPS;t++){
        {
            int row=tid>>1, k0=(tid&1)*8;
            union{uint4 q; unsigned short s[8];} hi,lo;
            #pragma unroll
            for(int j=0;j<8;j++){
                int k=k0+j;
                float v=(k<15)? state[(size_t)(bbase+row)*300+t*15+k] : (k==15?1.f:0.f);
                bfsplit(v,hi.s[j],lo.s[j]);
            }
            *(uint4*)(sm+OFF_A_HI+row*560+k0*2)=hi.q;
            *(uint4*)(sm+OFF_A_LO+row*560+k0*2)=lo.q;
        }
        __syncthreads();

        for(int np=0;np<4;np++){
            float aR[2][4][4],aZ[2][4][4],aH[2][4][4],aX[2][4][4];
            #pragma unroll
            for(int p=0;p<2;p++)
                #pragma unroll
                for(int m2=0;m2<4;m2++)
                    #pragma unroll
                    for(int e=0;e<4;e++){ aR[p][m2][e]=0.f;aZ[p][m2][e]=0.f;aH[p][m2][e]=0.f;aX[p][m2][e]=0.f; }

            uint32_t bxh[2][2],bxl[2][2];
            #pragma unroll
            for(int p=0;p<2;p++){
                uint32_t a0=sb+OFF_BXN + (np*64+p*32)*48 + bxoff;
                ldsm2(a0,bxh[p]); ldsm2(a0+12288,bxl[p]);
            }

            // stage chunk 0
            #pragma unroll
            for(int j=0;j<6;j++)
                cp16(sb+OFF_BS + sblk[j]*2560 + sn[j]*80 + su[j]*16,
                     g_Wg + shl[j]*208896 + (size_t)(sg[j]*256+np*64+sp[j]*32+sn[j])*272 + su[j]*8);
            CP_COMMIT(); CP_WAIT0(); __syncthreads();

            for(int kc=0;kc<9;kc++){
                int buf=kc&1;
                if(kc<8){
                    #pragma unroll
                    for(int j=0;j<6;j++)
                        cp16(sb+OFF_BS + (buf^1)*30720 + sblk[j]*2560 + sn[j]*80 + su[j]*16,
                             g_Wg + shl[j]*208896 + (size_t)(sg[j]*256+np*64+sp[j]*32+sn[j])*272
                                  + (kc+1)*32 + su[j]*8);
                    CP_COMMIT();
                }
                const int ns=(kc==8)?1:2;
                for(int s=0;s<ns;s++){
                    uint32_t bh[2][3][2], bl[2][3][2];
                    #pragma unroll
                    for(int p=0;p<2;p++)
                        #pragma unroll
                        for(int g=0;g<3;g++){
                            uint32_t base=sb+OFF_BS + buf*30720 + (p*6+g*2)*2560 + boffn + s*32;
                            ldsm2(base, bh[p][g]); ldsm2(base+2560, bl[p][g]);
                        }
                    #pragma unroll
                    for(int mt=0;mt<4;mt++){
                        uint32_t ah[4],al[4];
                        uint32_t abase=sb + (wm*64+mt*16)*560 + kc*64 + s*32 + aoff;
                        ldsm4(abase+OFF_A_HI, ah);
                        ldsm4(abase+OFF_A_LO, al);
                        #pragma unroll
                        for(int p=0;p<2;p++){
                            mma16816(aR[p][mt],ah,bh[p][0]); mma16816(aR[p][mt],al,bh[p][0]); mma16816(aR[p][mt],ah,bl[p][0]);
                            mma16816(aZ[p][mt],ah,bh[p][1]); mma16816(aZ[p][mt],al,bh[p][1]); mma16816(aZ[p][mt],ah,bl[p][1]);
                            mma16816(aH[p][mt],ah,bh[p][2]); mma16816(aH[p][mt],al,bh[p][2]); mma16816(aH[p][mt],ah,bl[p][2]);
                            if(kc==0 && s==0){
                                mma16816(aX[p][mt],ah,bxh[p]); mma16816(aX[p][mt],al,bxh[p]); mma16816(aX[p][mt],ah,bxl[p]);
                            }
                        }
                    }
                }
                if(kc<8){ CP_WAIT0(); __syncthreads(); }
            }
            // epilogue: gate math for both 32-col halves, stage h_new in gmem
            #pragma unroll
            for(int p=0;p<2;p++)
                #pragma unroll
                for(int mt=0;mt<4;mt++)
                    #pragma unroll
                    for(int e=0;e<4;e++){
                        int row=wm*64+mt*16+(l>>2)+(e>>1)*8;
                        int hcol=np*64+p*32+wn*8+2*(l&3)+(e&1);
                        float hp=__bfloat162float(*(__nv_bfloat16*)(sm+OFF_A_HI+row*560+(16+hcol)*2))
                                +__bfloat162float(*(__nv_bfloat16*)(sm+OFF_A_LO+row*560+(16+hcol)*2));
                        float r=sigmoidf_(aR[p][mt][e]), z=sigmoidf_(aZ[p][mt][e]);
                        float n=tanh_(fmaf(r,aH[p][mt][e],aX[p][mt][e]));
                        float hv=(1.f-z)*n+z*hp;
                        g_hstage[(size_t)cta*32768 + row*256 + hcol]=bfpack(hv);
                    }
            __syncthreads();   // all warps done with BS buf0 before next np restages
        } // np

        // commit staged h into A (h_t)
        {
            int row=tid>>1, cb=(tid&1)*128;
            const uint4* src=(const uint4*)(g_hstage + (size_t)cta*32768 + row*256 + cb);
            #pragma unroll
            for(int g8=0;g8<16;g8++){
                uint4 w0=src[g8*2], w1=src[g8*2+1];
                uint32_t ws[8]={w0.x,w0.y,w0.z,w0.w,w1.x,w1.y,w1.z,w1.w};
                union{uint4 q;unsigned short s[8];} hi,lo;
                #pragma unroll
                for(int j=0;j<8;j++){ hi.s[j]=(unsigned short)(ws[j]>>16); lo.s[j]=(unsigned short)(ws[j]&0xFFFFu); }
                *(uint4*)(sm+OFF_A_HI+row*560+(16+cb+g8*8)*2)=hi.q;
                *(uint4*)(sm+OFF_A_LO+row*560+(16+cb+g8*8)*2)=lo.q;
            }
        }
        __syncthreads();
    } // t

    for(int i=tid;i<128*288;i+=256){
        int r=i/288, c=i-r*288;
        uint32_t pk;
        if(c<15) pk=bfpack(state[(size_t)(bbase+r)*300+c]);
        else if(c==15 || c>=272) pk=0u;
        else pk=((uint32_t)(*(unsigned short*)(sm+OFF_A_HI+r*560+c*2))<<16)
               | (uint32_t)(*(unsigned short*)(sm+OFF_A_LO+r*560+c*2));
        g_xin[(size_t)(bbase+r)*288+c]=pk;
    }
}

// ---------------- MLP GEMM: mma.sync bf16-split, 128x128 tile (unchanged) ----------------
__global__ __launch_bounds__(256) void gemm_mma(const uint32_t* __restrict__ A,
        const unsigned short* __restrict__ W, const float* __restrict__ bias,
        uint32_t* __restrict__ C, int Kp, int N){
    extern __shared__ __align__(16) unsigned char sm[];
    const uint32_t sb=smem_u32(sm);
    const int tid=threadIdx.x, wid=tid>>5, l=tid&31;
    const int wm=wid&1, wn=wid>>1;
    const int nb=blockIdx.x*128, mb=blockIdx.y*128;
    const int nch=Kp>>5;
    const size_t wplane=(size_t)N*Kp;

    float acc[4][4][4];
    #pragma unroll
    for(int mt=0;mt<4;mt++)
        #pragma unroll
        for(int ng=0;ng<4;ng++)
            #pragma unroll
            for(int e=0;e<4;e++) acc[mt][ng][e]=0.f;

    const int arow=tid>>3, au=tid&7;
    const int brow=tid>>1, bu=tid&1;
    uint4 av[4], bv[2][2];

    #define LOAD_AB(kc) { \
        _Pragma("unroll") \
        for(int j=0;j<4;j++) \
            av[j]=*(const uint4*)(A + (size_t)(mb+arow+j*32)*Kp + (kc)*32 + au*4); \
        _Pragma("unroll") \
        for(int i2=0;i2<2;i2++){ \
            bv[0][i2]=*(const uint4*)(W + (size_t)(nb+brow)*Kp + (kc)*32 + bu*16 + i2*8); \
            bv[1][i2]=*(const uint4*)(W + wplane + (size_t)(nb+brow)*Kp + (kc)*32 + bu*16 + i2*8); } }
    #define STORE_AB(buf) { \
        _Pragma("unroll") \
        for(int j=0;j<4;j++){ \
            uint4 v=av[j]; int ro=(arow+j*32)*80+au*8; \
            *(uint2*)(sm + (buf)*20480 + ro) = \
                make_uint2((v.x>>16)|(v.y&0xffff0000u),(v.z>>16)|(v.w&0xffff0000u)); \
            *(uint2*)(sm + 10240 + (buf)*20480 + ro) = \
                make_uint2((v.x&0xffffu)|(v.y<<16),(v.z&0xffffu)|(v.w<<16)); } \
        _Pragma("unroll") \
        for(int i2=0;i2<2;i2++){ \
            *(uint4*)(sm + 40960 + (buf)*20480 + brow*80 + bu*32 + i2*16)=bv[0][i2]; \
            *(uint4*)(sm + 40960 + (buf)*20480 + 10240 + brow*80 + bu*32 + i2*16)=bv[1][i2]; } }

    LOAD_AB(0); STORE_AB(0);
    __syncthreads();

    const uint32_t aoff=(uint32_t)((l&15)*80 + (l>>4)*16);
    const uint32_t boff=(uint32_t)((wn*32+(l&7))*80 + ((l>>3)&1)*16);

    for(int kc=0;kc<nch;kc++){
        int buf=kc&1;
        if(kc+1<nch) LOAD_AB(kc+1);
        #pragma unroll
        for(int s=0;s<2;s++){
            uint32_t bh[4][2], bl[4][2];
            #pragma unroll
            for(int ng=0;ng<4;ng++){
                uint32_t base=sb + 40960 + buf*20480 + boff + ng*8*80 + s*32;
                ldsm2(base, bh[ng]); ldsm2(base+10240, bl[ng]);
            }
            #pragma unroll
            for(int mt=0;mt<4;mt++){
                uint32_t ah[4],al[4];
                uint32_t abase=sb + buf*20480 + (wm*64+mt*16)*80 + s*32 + aoff;
                ldsm4(abase, ah); ldsm4(abase+10240, al);
                #pragma unroll
                for(int ng=0;ng<4;ng++){
                    mma16816(acc[mt][ng],ah,bh[ng]);
                    mma16816(acc[mt][ng],al,bh[ng]);
                    mma16816(acc[mt][ng],ah,bl[ng]);
                }
            }
        }
        if(kc+1<nch){ STORE_AB(buf^1); __syncthreads(); }
    }

    #pragma unroll
    for(int mt=0;mt<4;mt++)
        #pragma unroll
        for(int ng=0;ng<4;ng++)
            #pragma unroll
            for(int e=0;e<4;e++){
                int row=mb + wm*64+mt*16+(l>>2)+(e>>1)*8;
                int col=nb + wn*32+ng*8+2*(l&3)+(e&1);
                float v=fmaxf(acc[mt][ng][e]+__ldg(bias+col),0.f);
                C[(size_t)row*N+col]=bfpack(v);
            }
    #undef LOAD_AB
    #undef STORE_AB
}

// ---------------- final layer ----------------
__global__ __launch_bounds__(256)
void final_kernel(const uint32_t* __restrict__ x4, const float* __restrict__ Wp,
                  const float* __restrict__ bp, float* __restrict__ out){
    int warp=(blockIdx.x*256+threadIdx.x)>>5, lane=threadIdx.x&31;
    if(warp>=B_TOT) return;
    const uint32_t* row=x4+(size_t)warp*256;
    float s=0.f;
    #pragma unroll
    for(int c=lane;c<256;c+=32) s+=bfunpk(row[c])*Wp[c];
    #pragma unroll
    for(int o=16;o;o>>=1) s+=__shfl_xor_sync(0xffffffffu,s,o);
    if(lane==0) out[warp]=tanh_(s+bp[0]);
}

// ---------------- host launcher ----------------
extern "C" void kernel_launch(void* const* d_in, const int* in_sizes, int n_in,
                              void* d_out, int out_size){
    const float* state=(const float*)d_in[0];
    const float* W_ih=(const float*)d_in[1];
    const float* W_hh=(const float*)d_in[2];
    const float* b_ih=(const float*)d_in[3];
    const float* b_hh=(const float*)d_in[4];
    const float* W1=(const float*)d_in[5];
    const float* b1=(const float*)d_in[6];
    const float* W2=(const float*)d_in[7];
    const float* b2=(const float*)d_in[8];
    const float* W3=(const float*)d_in[9];
    const float* b3=(const float*)d_in[10];
    const float* W4=(const float*)d_in[11];
    const float* b4=(const float*)d_in[12];
    const float* Wp=(const float*)d_in[13];
    const float* bp=(const float*)d_in[14];
    float* out=(float*)d_out;
    (void)in_sizes;(void)n_in;(void)out_size;

    void *pWm,*pxin,*px1,*px2,*px3,*px4;
    cudaGetSymbolAddress(&pWm,g_Wm);
    cudaGetSymbolAddress(&pxin,g_xin);
    cudaGetSymbolAddress(&px1,g_x1);
    cudaGetSymbolAddress(&px2,g_x2);
    cudaGetSymbolAddress(&px3,g_x3);
    cudaGetSymbolAddress(&px4,g_x4);
    unsigned short* Wm=(unsigned short*)pWm;

    pack_gru<<<768,272>>>(W_ih,W_hh,b_ih,b_hh);
    pack_mlp<<<1024,256>>>(W1, Wm+WO1, 1024, 271, 288, 1);
    pack_mlp<<<1024,256>>>(W2, Wm+WO2, 1024, 1024, 1024, 0);
    pack_mlp<<<512,256>>>(W3, Wm+WO3, 512, 1024, 1024, 0);
    pack_mlp<<<256,256>>>(W4, Wm+WO4, 256, 512, 512, 0);

    cudaFuncSetAttribute(gru_mma_kernel, cudaFuncAttributeMaxDynamicSharedMemorySize, GRU_SMEM);
    gru_mma_kernel<<<128,256,GRU_SMEM>>>(state);

    cudaFuncSetAttribute(gemm_mma, cudaFuncAttributeMaxDynamicSharedMemorySize, MLP_SMEM);
    gemm_mma<<<dim3(8,128),256,MLP_SMEM>>>((const uint32_t*)pxin, Wm+WO1, b1, (uint32_t*)px1, 288, 1024);
    gemm_mma<<<dim3(8,128),256,MLP_SMEM>>>((const uint32_t*)px1,  Wm+WO2, b2, (uint32_t*)px2, 1024, 1024);
    gemm_mma<<<dim3(4,128),256,MLP_SMEM>>>((const uint32_t*)px2,  Wm+WO3, b3, (uint32_t*)px3, 1024, 512);
    gemm_mma<<<dim3(2,128),256,MLP_SMEM>>>((const uint32_t*)px3,  Wm+WO4, b4, (uint32_t*)px4, 512, 256);
    final_kernel<<<B_TOT/8,256>>>((const uint32_t*)px4, Wp, bp, out);
}

// round 14
// speedup vs baseline: 1.1245x; 1.1245x over previous
#include <cuda_runtime.h>
#include <cuda_bf16.h>
#include <stdint.h>

#define B_TOT 16384
#define V_STEPS 20

// ---- activation buffers: packed bf16 pair (hi<<16 | lo) per element ----
__device__ uint32_t g_xin[B_TOT*288];
__device__ uint32_t g_x1[B_TOT*1024];
__device__ uint32_t g_x2[B_TOT*1024];
__device__ uint32_t g_x3[B_TOT*512];
__device__ uint32_t g_x4[B_TOT*256];
// MLP weights bf16 planes [hl][N][Kp] per layer, concatenated
#define WO1 0
#define WO2 589824
#define WO3 (WO2+2097152)
#define WO4 (WO3+1048576)
__device__ __align__(16) unsigned short g_Wm[WO4+262144];
// GRU packed weights bf16 [hl][768][272] (+pad)
__device__ __align__(16) unsigned short g_Wg[2*768*272 + 64];
__device__ __align__(16) unsigned short g_Wxn[2*256*16];
__device__ uint32_t g_hstage[128*128*256];

// GRU smem offsets
#define OFF_A_HI 0
#define OFF_A_LO 71680
#define OFF_BXN  143360            // [2 planes][256 rows][48B]
#define OFF_BS   167936            // [2 wg][2 buf][6 blk][32 rows][48B] = 36864
#define GRU_SMEM 204800
#define MLP_SMEM 81920

__device__ __forceinline__ float sigmoidf_(float x){ return __fdividef(1.f,1.f+__expf(-x)); }
__device__ __forceinline__ float tanh_(float x){ return __fdividef(2.f,1.f+__expf(-2.f*x))-1.f; }
__device__ __forceinline__ uint32_t smem_u32(const void* p){
    uint32_t a; asm("{ .reg .u64 t; cvta.to.shared.u64 t, %1; cvt.u32.u64 %0, t; }":"=r"(a):"l"(p)); return a;
}
__device__ __forceinline__ void ldsm4(uint32_t a, uint32_t* r){
    asm volatile("ldmatrix.sync.aligned.m8n8.x4.shared.b16 {%0,%1,%2,%3}, [%4];"
        : "=r"(r[0]),"=r"(r[1]),"=r"(r[2]),"=r"(r[3]) : "r"(a));
}
__device__ __forceinline__ void ldsm2(uint32_t a, uint32_t* r){
    asm volatile("ldmatrix.sync.aligned.m8n8.x2.shared.b16 {%0,%1}, [%2];"
        : "=r"(r[0]),"=r"(r[1]) : "r"(a));
}
__device__ __forceinline__ void mma16816(float* d, const uint32_t* a, const uint32_t* b){
    asm volatile("mma.sync.aligned.m16n8k16.row.col.f32.bf16.bf16.f32 "
        "{%0,%1,%2,%3}, {%4,%5,%6,%7}, {%8,%9}, {%0,%1,%2,%3};"
        : "+f"(d[0]),"+f"(d[1]),"+f"(d[2]),"+f"(d[3])
        : "r"(a[0]),"r"(a[1]),"r"(a[2]),"r"(a[3]),"r"(b[0]),"r"(b[1]));
}
__device__ __forceinline__ void cp16(uint32_t dst, const void* src){
    asm volatile("cp.async.cg.shared.global [%0], [%1], 16;"::"r"(dst),"l"(src));
}
#define CP_COMMIT() asm volatile("cp.async.commit_group;":::"memory")
#define CP_WAIT0()  asm volatile("cp.async.wait_group 0;":::"memory")
__device__ __forceinline__ void bfsplit(float v, unsigned short& h, unsigned short& l){
    __nv_bfloat16 hh=__float2bfloat16(v);
    h=__bfloat16_as_ushort(hh);
    l=__bfloat16_as_ushort(__float2bfloat16(v-__bfloat162float(hh)));
}
__device__ __forceinline__ uint32_t bfpack(float v){
    unsigned short h,l; bfsplit(v,h,l); return ((uint32_t)h<<16)|l;
}
__device__ __forceinline__ float bfunpk(uint32_t p){
    unsigned short h=(unsigned short)(p>>16), l=(unsigned short)(p&0xffffu);
    return __bfloat162float(*(__nv_bfloat16*)&h)+__bfloat162float(*(__nv_bfloat16*)&l);
}

// ---------------- pack kernels ----------------
__global__ void pack_gru(const float* __restrict__ W_ih, const float* __restrict__ W_hh,
                         const float* __restrict__ b_ih, const float* __restrict__ b_hh){
    int g=blockIdx.x, k=threadIdx.x;
    int gate=g>>8;
    float v;
    if(k<15)       v = (gate==2)? 0.f : W_ih[g*15+k];
    else if(k==15) v = (gate==2)? b_hh[g] : (b_ih[g]+b_hh[g]);
    else           v = W_hh[g*256+(k-16)];
    unsigned short h,l; bfsplit(v,h,l);
    g_Wg[g*272+k]=h; g_Wg[208896+g*272+k]=l;
    if(g>=512 && k<16){
        float w = (k<15)? W_ih[g*15+k] : b_ih[g];
        unsigned short h2,l2; bfsplit(w,h2,l2);
        g_Wxn[(g-512)*16+k]=h2; g_Wxn[4096+(g-512)*16+k]=l2;
    }
}
__global__ void pack_mlp(const float* __restrict__ W, unsigned short* __restrict__ dst,
                         int N, int K, int Kp, int l1mode){
    int n=blockIdx.x;
    for(int k=threadIdx.x;k<Kp;k+=256){
        float v=0.f;
        if(l1mode){ if(k<15) v=W[n*271+k]; else if(k>=16&&k<272) v=W[n*271+k-1]; }
        else if(k<K) v=W[(size_t)n*K+k];
        unsigned short h,l; bfsplit(v,h,l);
        dst[(size_t)n*Kp+k]=h;
        dst[(size_t)N*Kp+(size_t)n*Kp+k]=l;
    }
}

// ---------------- GRU: mma.sync bf16-split, 2 warp-groups over N ----------------
__global__ __launch_bounds__(512,1) void gru_mma_kernel(const float* __restrict__ state){
    extern __shared__ __align__(16) unsigned char sm[];
    const uint32_t sb=smem_u32(sm);
    const int tid=threadIdx.x, wid=tid>>5, l=tid&31, ll=l&15;
    const int wg=wid>>3, wid8=wid&7, wm=wid8&1, wn=wid8>>1;
    const int wgtid=tid&255;
    const int cta=blockIdx.x, bbase=cta*128;
    const uint32_t bs_wg = sb + OFF_BS + wg*18432;

    for(int i=tid;i<143360/16;i+=512) ((uint4*)sm)[i]=make_uint4(0,0,0,0);
    for(int i=tid;i<1024;i+=512){
        int u=i&1, n=(i>>1)&255, hl=i>>9;
        uint4 v=*(const uint4*)(g_Wxn + hl*4096 + n*16 + u*8);
        *(uint4*)(sm+OFF_BXN + hl*12288 + n*48 + u*16)=v;
    }
    __syncthreads();

    const uint32_t aoff  = (uint32_t)(ll*560 + (l>>4)*16);
    const uint32_t boffn = (uint32_t)((l&7)*48 + (ll>>3)*16) + wn*8*48;
    const uint32_t bxoff = (uint32_t)((l&7)*48 + (ll>>3)*16) + wn*8*48;

    #define BARWG() asm volatile("bar.sync %0, %1;"::"r"(wg+1),"r"(256):"memory")
    // stage one 16-k chunk of 3 gate x hi/lo B tiles for this wg's hb
    #define STAGE(kc_, bufb, hb_) { \
        _Pragma("unroll") \
        for(int j=0;j<2;j++){ int i=wgtid+j*256; if(i<384){ \
            int blk=i>>6, r2=(i>>1)&31, half=i&1; \
            int gg=blk>>1, hl2=blk&1; \
            cp16(bs_wg + (bufb)*9216 + blk*1536 + r2*48 + half*16, \
                 g_Wg + hl2*208896 + (size_t)(gg*256+(hb_)*32+r2)*272 + (kc_)*16 + half*8); } } }

    for(int t=0;t<V_STEPS;t++){
        if(tid<256){
            int row=tid>>1, k0=(tid&1)*8;
            union{uint4 q; unsigned short s[8];} hi,lo;
            #pragma unroll
            for(int j=0;j<8;j++){
                int k=k0+j;
                float v=(k<15)? state[(size_t)(bbase+row)*300+t*15+k] : (k==15?1.f:0.f);
                bfsplit(v,hi.s[j],lo.s[j]);
            }
            *(uint4*)(sm+OFF_A_HI+row*560+k0*2)=hi.q;
            *(uint4*)(sm+OFF_A_LO+row*560+k0*2)=lo.q;
        }
        __syncthreads();

        for(int ii=0;ii<4;ii++){
            const int hb=ii*2+wg;
            float aR[4][4],aZ[4][4],aH[4][4],aX[4][4];
            #pragma unroll
            for(int m2=0;m2<4;m2++)
                #pragma unroll
                for(int e=0;e<4;e++){ aR[m2][e]=0.f;aZ[m2][e]=0.f;aH[m2][e]=0.f;aX[m2][e]=0.f; }

            uint32_t bxh[2],bxl[2];
            { uint32_t a0=sb+OFF_BXN + hb*32*48 + bxoff;
              ldsm2(a0,bxh); ldsm2(a0+12288,bxl); }

            STAGE(0,0,hb); CP_COMMIT(); CP_WAIT0(); BARWG();

            for(int kc=0;kc<17;kc++){
                int buf=kc&1;
                if(kc<16){ STAGE(kc+1,buf^1,hb); CP_COMMIT(); }
                uint32_t bh[3][2], bl[3][2];
                #pragma unroll
                for(int g=0;g<3;g++){
                    uint32_t base=bs_wg + buf*9216 + (g*2)*1536 + boffn;
                    ldsm2(base, bh[g]); ldsm2(base+1536, bl[g]);
                }
                #pragma unroll
                for(int mt=0;mt<4;mt++){
                    uint32_t ah[4],al[4];
                    uint32_t abase=sb + (wm*64+mt*16)*560 + kc*32 + aoff;
                    ldsm4(abase+OFF_A_HI, ah);
                    ldsm4(abase+OFF_A_LO, al);
                    mma16816(aR[mt],ah,bh[0]); mma16816(aR[mt],al,bh[0]); mma16816(aR[mt],ah,bl[0]);
                    mma16816(aZ[mt],ah,bh[1]); mma16816(aZ[mt],al,bh[1]); mma16816(aZ[mt],ah,bl[1]);
                    mma16816(aH[mt],ah,bh[2]); mma16816(aH[mt],al,bh[2]); mma16816(aH[mt],ah,bl[2]);
                    if(kc==0){
                        mma16816(aX[mt],ah,bxh); mma16816(aX[mt],al,bxh); mma16816(aX[mt],ah,bxl);
                    }
                }
                if(kc<16){ CP_WAIT0(); BARWG(); }
            }
            // epilogue: gate math, stage h_new in gmem
            #pragma unroll
            for(int mt=0;mt<4;mt++)
                #pragma unroll
                for(int e=0;e<4;e++){
                    int row=wm*64+mt*16+(l>>2)+(e>>1)*8;
                    int hcol=hb*32+wn*8+2*(l&3)+(e&1);
                    float hp=__bfloat162float(*(__nv_bfloat16*)(sm+OFF_A_HI+row*560+(16+hcol)*2))
                            +__bfloat162float(*(__nv_bfloat16*)(sm+OFF_A_LO+row*560+(16+hcol)*2));
                    float r=sigmoidf_(aR[mt][e]), z=sigmoidf_(aZ[mt][e]);
                    float n=tanh_(fmaf(r,aH[mt][e],aX[mt][e]));
                    float hv=(1.f-z)*n+z*hp;
                    g_hstage[(size_t)cta*32768 + row*256 + hcol]=bfpack(hv);
                }
            BARWG();    // all wg warps done reading BS before next hb restages
        } // ii

        __syncthreads();
        if(tid<256){
            int row=tid>>1, cb=(tid&1)*128;
            const uint4* src=(const uint4*)(g_hstage + (size_t)cta*32768 + row*256 + cb);
            #pragma unroll
            for(int g8=0;g8<16;g8++){
                uint4 w0=src[g8*2], w1=src[g8*2+1];
                uint32_t ws[8]={w0.x,w0.y,w0.z,w0.w,w1.x,w1.y,w1.z,w1.w};
                union{uint4 q;unsigned short s[8];} hi,lo;
                #pragma unroll
                for(int j=0;j<8;j++){ hi.s[j]=(unsigned short)(ws[j]>>16); lo.s[j]=(unsigned short)(ws[j]&0xFFFFu); }
                *(uint4*)(sm+OFF_A_HI+row*560+(16+cb+g8*8)*2)=hi.q;
                *(uint4*)(sm+OFF_A_LO+row*560+(16+cb+g8*8)*2)=lo.q;
            }
        }
        __syncthreads();
    } // t

    for(int i=tid;i<128*288;i+=512){
        int r=i/288, c=i-r*288;
        uint32_t pk;
        if(c<15) pk=bfpack(state[(size_t)(bbase+r)*300+c]);
        else if(c==15 || c>=272) pk=0u;
        else pk=((uint32_t)(*(unsigned short*)(sm+OFF_A_HI+r*560+c*2))<<16)
               | (uint32_t)(*(unsigned short*)(sm+OFF_A_LO+r*560+c*2));
        g_xin[(size_t)(bbase+r)*288+c]=pk;
    }
    #undef STAGE
    #undef BARWG
}

// ---------------- MLP GEMM: mma.sync bf16-split, 128x128 tile (R11, proven) ----------------
__global__ __launch_bounds__(256) void gemm_mma(const uint32_t* __restrict__ A,
        const unsigned short* __restrict__ W, const float* __restrict__ bias,
        uint32_t* __restrict__ C, int Kp, int N){
    extern __shared__ __align__(16) unsigned char sm[];
    const uint32_t sb=smem_u32(sm);
    const int tid=threadIdx.x, wid=tid>>5, l=tid&31;
    const int wm=wid&1, wn=wid>>1;
    const int nb=blockIdx.x*128, mb=blockIdx.y*128;
    const int nch=Kp>>5;
    const size_t wplane=(size_t)N*Kp;

    float acc[4][4][4];
    #pragma unroll
    for(int mt=0;mt<4;mt++)
        #pragma unroll
        for(int ng=0;ng<4;ng++)
            #pragma unroll
            for(int e=0;e<4;e++) acc[mt][ng][e]=0.f;

    const int arow=tid>>3, au=tid&7;
    const int brow=tid>>1, bu=tid&1;
    uint4 av[4], bv[2][2];

    #define LOAD_AB(kc) { \
        _Pragma("unroll") \
        for(int j=0;j<4;j++) \
            av[j]=*(const uint4*)(A + (size_t)(mb+arow+j*32)*Kp + (kc)*32 + au*4); \
        _Pragma("unroll") \
        for(int i2=0;i2<2;i2++){ \
            bv[0][i2]=*(const uint4*)(W + (size_t)(nb+brow)*Kp + (kc)*32 + bu*16 + i2*8); \
            bv[1][i2]=*(const uint4*)(W + wplane + (size_t)(nb+brow)*Kp + (kc)*32 + bu*16 + i2*8); } }
    #define STORE_AB(buf) { \
        _Pragma("unroll") \
        for(int j=0;j<4;j++){ \
            uint4 v=av[j]; int ro=(arow+j*32)*80+au*8; \
            *(uint2*)(sm + (buf)*20480 + ro) = \
                make_uint2((v.x>>16)|(v.y&0xffff0000u),(v.z>>16)|(v.w&0xffff0000u)); \
            *(uint2*)(sm + 10240 + (buf)*20480 + ro) = \
                make_uint2((v.x&0xffffu)|(v.y<<16),(v.z&0xffffu)|(v.w<<16)); } \
        _Pragma("unroll") \
        for(int i2=0;i2<2;i2++){ \
            *(uint4*)(sm + 40960 + (buf)*20480 + brow*80 + bu*32 + i2*16)=bv[0][i2]; \
            *(uint4*)(sm + 40960 + (buf)*20480 + 10240 + brow*80 + bu*32 + i2*16)=bv[1][i2]; } }

    LOAD_AB(0); STORE_AB(0);
    __syncthreads();

    const uint32_t aoff=(uint32_t)((l&15)*80 + (l>>4)*16);
    const uint32_t boff=(uint32_t)((wn*32+(l&7))*80 + ((l>>3)&1)*16);

    for(int kc=0;kc<nch;kc++){
        int buf=kc&1;
        if(kc+1<nch) LOAD_AB(kc+1);
        #pragma unroll
        for(int s=0;s<2;s++){
            uint32_t bh[4][2], bl[4][2];
            #pragma unroll
            for(int ng=0;ng<4;ng++){
                uint32_t base=sb + 40960 + buf*20480 + boff + ng*8*80 + s*32;
                ldsm2(base, bh[ng]); ldsm2(base+10240, bl[ng]);
            }
            #pragma unroll
            for(int mt=0;mt<4;mt++){
                uint32_t ah[4],al[4];
                uint32_t abase=sb + buf*20480 + (wm*64+mt*16)*80 + s*32 + aoff;
                ldsm4(abase, ah); ldsm4(abase+10240, al);
                #pragma unroll
                for(int ng=0;ng<4;ng++){
                    mma16816(acc[mt][ng],ah,bh[ng]);
                    mma16816(acc[mt][ng],al,bh[ng]);
                    mma16816(acc[mt][ng],ah,bl[ng]);
                }
            }
        }
        if(kc+1<nch){ STORE_AB(buf^1); __syncthreads(); }
    }

    #pragma unroll
    for(int mt=0;mt<4;mt++)
        #pragma unroll
        for(int ng=0;ng<4;ng++)
            #pragma unroll
            for(int e=0;e<4;e++){
                int row=mb + wm*64+mt*16+(l>>2)+(e>>1)*8;
                int col=nb + wn*32+ng*8+2*(l&3)+(e&1);
                float v=fmaxf(acc[mt][ng][e]+__ldg(bias+col),0.f);
                C[(size_t)row*N+col]=bfpack(v);
            }
    #undef LOAD_AB
    #undef STORE_AB
}

// ---------------- final layer ----------------
__global__ __launch_bounds__(256)
void final_kernel(const uint32_t* __restrict__ x4, const float* __restrict__ Wp,
                  const float* __restrict__ bp, float* __restrict__ out){
    int warp=(blockIdx.x*256+threadIdx.x)>>5, lane=threadIdx.x&31;
    if(warp>=B_TOT) return;
    const uint32_t* row=x4+(size_t)warp*256;
    float s=0.f;
    #pragma unroll
    for(int c=lane;c<256;c+=32) s+=bfunpk(row[c])*Wp[c];
    #pragma unroll
    for(int o=16;o;o>>=1) s+=__shfl_xor_sync(0xffffffffu,s,o);
    if(lane==0) out[warp]=tanh_(s+bp[0]);
}

// ---------------- host launcher ----------------
extern "C" void kernel_launch(void* const* d_in, const int* in_sizes, int n_in,
                              void* d_out, int out_size){
    const float* state=(const float*)d_in[0];
    const float* W_ih=(const float*)d_in[1];
    const float* W_hh=(const float*)d_in[2];
    const float* b_ih=(const float*)d_in[3];
    const float* b_hh=(const float*)d_in[4];
    const float* W1=(const float*)d_in[5];
    const float* b1=(const float*)d_in[6];
    const float* W2=(const float*)d_in[7];
    const float* b2=(const float*)d_in[8];
    const float* W3=(const float*)d_in[9];
    const float* b3=(const float*)d_in[10];
    const float* W4=(const float*)d_in[11];
    const float* b4=(const float*)d_in[12];
    const float* Wp=(const float*)d_in[13];
    const float* bp=(const float*)d_in[14];
    float* out=(float*)d_out;
    (void)in_sizes;(void)n_in;(void)out_size;

    void *pWm,*pxin,*px1,*px2,*px3,*px4;
    cudaGetSymbolAddress(&pWm,g_Wm);
    cudaGetSymbolAddress(&pxin,g_xin);
    cudaGetSymbolAddress(&px1,g_x1);
    cudaGetSymbolAddress(&px2,g_x2);
    cudaGetSymbolAddress(&px3,g_x3);
    cudaGetSymbolAddress(&px4,g_x4);
    unsigned short* Wm=(unsigned short*)pWm;

    pack_gru<<<768,272>>>(W_ih,W_hh,b_ih,b_hh);
    pack_mlp<<<1024,256>>>(W1, Wm+WO1, 1024, 271, 288, 1);
    pack_mlp<<<1024,256>>>(W2, Wm+WO2, 1024, 1024, 1024, 0);
    pack_mlp<<<512,256>>>(W3, Wm+WO3, 512, 1024, 1024, 0);
    pack_mlp<<<256,256>>>(W4, Wm+WO4, 256, 512, 512, 0);

    cudaFuncSetAttribute(gru_mma_kernel, cudaFuncAttributeMaxDynamicSharedMemorySize, GRU_SMEM);
    gru_mma_kernel<<<128,512,GRU_SMEM>>>(state);

    cudaFuncSetAttribute(gemm_mma, cudaFuncAttributeMaxDynamicSharedMemorySize, MLP_SMEM);
    gemm_mma<<<dim3(8,128),256,MLP_SMEM>>>((const uint32_t*)pxin, Wm+WO1, b1, (uint32_t*)px1, 288, 1024);
    gemm_mma<<<dim3(8,128),256,MLP_SMEM>>>((const uint32_t*)px1,  Wm+WO2, b2, (uint32_t*)px2, 1024, 1024);
    gemm_mma<<<dim3(4,128),256,MLP_SMEM>>>((const uint32_t*)px2,  Wm+WO3, b3, (uint32_t*)px3, 1024, 512);
    gemm_mma<<<dim3(2,128),256,MLP_SMEM>>>((const uint32_t*)px3,  Wm+WO4, b4, (uint32_t*)px4, 512, 256);
    final_kernel<<<B_TOT/8,256>>>((const uint32_t*)px4, Wp, bp, out);
}